// round 14
// baseline (speedup 1.0000x reference)
#include <cuda_runtime.h>
#include <cuda_fp16.h>

#define D 128
#define NTHREADS 512
#define CTAS_PER_SM 2
#define NBLOCKS (152 * CTAS_PER_SM)

// Combined fp16 tables (rows of 128 halves = 256B)
#define R_T1  46               // E_atom + bias
#define R_DH  18               // deg(6) x hyb(3)
#define R_HCG 220              // numh(5) x chiral(4) x charge(11)
#define R_B0  25               // (c0,c1): masked E_bond + c/4*(W3,W4)
#define R_B1  25               // (c2,c3): masked E_bond + c/4*(W5,W6)
#define R_TOT (R_T1 + R_DH + R_HCG + R_B0 + R_B1)   // 334

#define ROW_T1  0
#define ROW_DH  (ROW_T1 + R_T1)    // 46
#define ROW_HCG (ROW_DH + R_DH)    // 64
#define ROW_B0  (ROW_HCG + R_HCG)  // 284
#define ROW_B1  (ROW_B0 + R_B0)    // 309

#define SMEM_BYTES (R_TOT * D * 2)  // 85504 B -> 2 CTAs/SM

__device__ __forceinline__ unsigned hadd2u(unsigned a, unsigned b) {
    __half2 r = __hadd2(*reinterpret_cast<__half2*>(&a),
                        *reinterpret_cast<__half2*>(&b));
    return *reinterpret_cast<unsigned*>(&r);
}
__device__ __forceinline__ uint4 hadd8(uint4 a, uint4 b) {
    uint4 r;
    r.x = hadd2u(a.x, b.x); r.y = hadd2u(a.y, b.y);
    r.z = hadd2u(a.z, b.z); r.w = hadd2u(a.w, b.w);
    return r;
}
__device__ __forceinline__ float lo2f(unsigned u) {
    return __low2float(*reinterpret_cast<__half2*>(&u));
}
__device__ __forceinline__ float hi2f(unsigned u) {
    return __high2float(*reinterpret_cast<__half2*>(&u));
}

// Per-lane coalesced metadata load for one atom.
// pack bits: ai[0:6) rdh[6:11) rhcg[11:19) rb0[19:24) rb1[24:29)
__device__ __forceinline__ void load_meta_lane(
    long a, long n, float& s0, float& s1, float& s2, unsigned& p,
    const int* __restrict__ atom_idx, const int* __restrict__ degree_idx,
    const int* __restrict__ charge_idx, const int* __restrict__ hybrid_idx,
    const int* __restrict__ numh_idx, const int* __restrict__ chiral_idx,
    const int* __restrict__ bond_counts, const float* __restrict__ scalar3)
{
    if (a < n) {
        const int ai = __ldcs(atom_idx + a);
        const int di = __ldcs(degree_idx + a);
        const int ci = __ldcs(charge_idx + a);
        const int hi = __ldcs(hybrid_idx + a);
        const int ni = __ldcs(numh_idx + a);
        const int xi = __ldcs(chiral_idx + a);
        const int4 bc = __ldcs(reinterpret_cast<const int4*>(bond_counts) + a);
        p = (unsigned)ai
          | ((unsigned)(di * 3 + hi)              << 6)
          | ((unsigned)((ni * 4 + xi) * 11 + ci)  << 11)
          | ((unsigned)(bc.x * 5 + bc.y)          << 19)
          | ((unsigned)(bc.z * 5 + bc.w)          << 24);
        s0 = __ldcs(scalar3 + 3 * a + 0);
        s1 = __ldcs(scalar3 + 3 * a + 1);
        s2 = __ldcs(scalar3 + 3 * a + 2);
    } else {
        p = 0u; s0 = 0.f; s1 = 0.f; s2 = 0.f;
    }
}

__global__ void __launch_bounds__(NTHREADS, CTAS_PER_SM)
atom_featurizer_kernel(
    const int* __restrict__ atom_idx,
    const int* __restrict__ degree_idx,
    const int* __restrict__ charge_idx,
    const int* __restrict__ hybrid_idx,
    const int* __restrict__ numh_idx,
    const int* __restrict__ chiral_idx,
    const int* __restrict__ bond_counts,
    const float* __restrict__ scalar3,
    const float* __restrict__ E_atom,
    const float* __restrict__ E_deg,
    const float* __restrict__ E_chg,
    const float* __restrict__ E_hyb,
    const float* __restrict__ E_h,
    const float* __restrict__ E_chi,
    const float* __restrict__ E_bond,
    const float* __restrict__ Wm,
    const float* __restrict__ bv,
    float* __restrict__ out,
    long n)
{
    extern __shared__ __align__(16) char smem_raw[];
    __half* sh = reinterpret_cast<__half*>(smem_raw);

    const int t = threadIdx.x;

    // ---- Build combined fp16 tables (once per persistent CTA) ----
    for (int e = t; e < R_TOT * D; e += NTHREADS) {
        const int row = e >> 7, col = e & (D - 1);
        float v;
        if (row < ROW_DH) {                        // T1: atom + bias
            v = E_atom[row * D + col] + bv[col];
        } else if (row < ROW_HCG) {                // DH: deg x hyb
            int r = row - ROW_DH;
            v = E_deg[(r / 3) * D + col] + E_hyb[(r % 3) * D + col];
        } else if (row < ROW_B0) {                 // HCG: numh x chiral x charge
            int r = row - ROW_HCG;
            int ni = r / 44, rem = r % 44;
            int xi = rem / 11, ci = rem % 11;
            v = E_h[ni * D + col] + E_chi[xi * D + col] + E_chg[ci * D + col];
        } else if (row < ROW_B1) {                 // B0: (c0,c1)
            int r = row - ROW_B0;
            int c0 = r / 5, c1 = r % 5;
            v = 0.25f * (c0 * Wm[3 * D + col] + c1 * Wm[4 * D + col]);
            if (c0 > 0) v += E_bond[c0 * D + col];
            if (c1 > 0) v += E_bond[c1 * D + col];
        } else {                                   // B1: (c2,c3)
            int r = row - ROW_B1;
            int c2 = r / 5, c3 = r % 5;
            v = 0.25f * (c2 * Wm[5 * D + col] + c3 * Wm[6 * D + col]);
            if (c2 > 0) v += E_bond[c2 * D + col];
            if (c3 > 0) v += E_bond[c3 * D + col];
        }
        sh[e] = __float2half_rn(v);
    }

    const int lane = t & 31;
    const int warp = t >> 5;
    const int j = lane & 15;       // 16B chunk within row (dims [8j, 8j+8))
    const int sub = lane >> 4;     // 0 -> even atom, 1 -> odd atom

    // W rows 0..2 slices as half2 registers
    __half2 w0h[4], w1h[4], w2h[4];
    #pragma unroll
    for (int q = 0; q < 4; q++) {
        w0h[q] = __floats2half2_rn(Wm[0 * D + j * 8 + 2 * q],
                                   Wm[0 * D + j * 8 + 2 * q + 1]);
        w1h[q] = __floats2half2_rn(Wm[1 * D + j * 8 + 2 * q],
                                   Wm[1 * D + j * 8 + 2 * q + 1]);
        w2h[q] = __floats2half2_rn(Wm[2 * D + j * 8 + 2 * q],
                                   Wm[2 * D + j * 8 + 2 * q + 1]);
    }

    __syncthreads();   // tables ready; no barriers after this point

    const uint4* tab = reinterpret_cast<const uint4*>(sh);  // 16 uint4 per row
    float4* out4 = reinterpret_cast<float4*>(out);

    // Persistent warps, chunks of 32 atoms
    const long nchunks = (n + 31) >> 5;
    const long nwarps = (long)gridDim.x * (NTHREADS / 32);
    long chunk = (long)blockIdx.x * (NTHREADS / 32) + warp;

    // Prefetch chunk 0 metadata (one atom per lane, coalesced)
    float cs0, cs1, cs2; unsigned cp;
    if (chunk < nchunks)
        load_meta_lane(chunk * 32 + lane, n, cs0, cs1, cs2, cp,
                       atom_idx, degree_idx, charge_idx, hybrid_idx,
                       numh_idx, chiral_idx, bond_counts, scalar3);

    for (; chunk < nchunks; chunk += nwarps) {
        // Issue next chunk's loads; they complete under this chunk's compute
        float ns0, ns1, ns2; unsigned np;
        const long nxt = chunk + nwarps;
        if (nxt < nchunks)
            load_meta_lane(nxt * 32 + lane, n, ns0, ns1, ns2, np,
                           atom_idx, degree_idx, charge_idx, hybrid_idx,
                           numh_idx, chiral_idx, bond_counts, scalar3);

        const long gbase = chunk * 32;

        #pragma unroll 4
        for (int k = 0; k < 16; k++) {
            const int src = 2 * k + sub;           // atom-in-chunk for this half-warp
            const long g = gbase + src;

            const float    m0 = __shfl_sync(0xffffffffu, cs0, src);
            const float    m1 = __shfl_sync(0xffffffffu, cs1, src);
            const float    m2 = __shfl_sync(0xffffffffu, cs2, src);
            const unsigned p  = __shfl_sync(0xffffffffu, cp,  src);

            const int i1 =  p         & 63;
            const int i2 = ((p >> 6)  & 31)  + ROW_DH;
            const int i3 = ((p >> 11) & 255) + ROW_HCG;
            const int i4 = ((p >> 19) & 31)  + ROW_B0;
            const int i5 = ((p >> 24) & 31)  + ROW_B1;

            // 5 independent LDS.128 for max MLP
            const uint4 t1  = tab[i1 * 16 + j];
            const uint4 dh  = tab[i2 * 16 + j];
            const uint4 hcg = tab[i3 * 16 + j];
            const uint4 b0  = tab[i4 * 16 + j];
            const uint4 b1  = tab[i5 * 16 + j];

            // Subtree A: categorical lookups
            const uint4 sA = hadd8(hadd8(t1, dh), hcg);
            // Subtree B: bond tables + s.W in half2
            uint4 sB = hadd8(b0, b1);
            {
                const __half2 s0h = __float2half2_rn(m0);
                const __half2 s1h = __float2half2_rn(m1);
                const __half2 s2h = __float2half2_rn(m2);
                unsigned* sw = &sB.x;
                #pragma unroll
                for (int q = 0; q < 4; q++) {
                    __half2 acc = __hmul2(s0h, w0h[q]);
                    acc = __hfma2(s1h, w1h[q], acc);
                    acc = __hfma2(s2h, w2h[q], acc);
                    sw[q] = hadd2u(sw[q], *reinterpret_cast<unsigned*>(&acc));
                }
            }

            // fp32 combine
            float4 olo, ohi;
            olo.x = lo2f(sA.x) + lo2f(sB.x);
            olo.y = hi2f(sA.x) + hi2f(sB.x);
            olo.z = lo2f(sA.y) + lo2f(sB.y);
            olo.w = hi2f(sA.y) + hi2f(sB.y);
            ohi.x = lo2f(sA.z) + lo2f(sB.z);
            ohi.y = hi2f(sA.z) + hi2f(sB.z);
            ohi.z = lo2f(sA.w) + lo2f(sB.w);
            ohi.w = hi2f(sA.w) + hi2f(sB.w);

            if (g < n) {
                __stcs(&out4[g * 32 + j * 2],     olo);
                __stcs(&out4[g * 32 + j * 2 + 1], ohi);
            }
        }

        cs0 = ns0; cs1 = ns1; cs2 = ns2; cp = np;
    }
}

extern "C" void kernel_launch(void* const* d_in, const int* in_sizes, int n_in,
                              void* d_out, int out_size) {
    const int*   atom_idx    = (const int*)d_in[0];
    const int*   degree_idx  = (const int*)d_in[1];
    const int*   charge_idx  = (const int*)d_in[2];
    const int*   hybrid_idx  = (const int*)d_in[3];
    const int*   numh_idx    = (const int*)d_in[4];
    const int*   chiral_idx  = (const int*)d_in[5];
    const int*   bond_counts = (const int*)d_in[6];
    const float* scalar3     = (const float*)d_in[7];
    const float* E_atom      = (const float*)d_in[8];
    const float* E_deg       = (const float*)d_in[9];
    const float* E_chg       = (const float*)d_in[10];
    const float* E_hyb       = (const float*)d_in[11];
    const float* E_h         = (const float*)d_in[12];
    const float* E_chi       = (const float*)d_in[13];
    const float* E_bond      = (const float*)d_in[14];
    const float* Wm          = (const float*)d_in[15];
    const float* bv          = (const float*)d_in[16];
    float* out = (float*)d_out;

    const long n = in_sizes[0];

    static bool attr_set = false;
    if (!attr_set) {
        cudaFuncSetAttribute(atom_featurizer_kernel,
                             cudaFuncAttributeMaxDynamicSharedMemorySize, SMEM_BYTES);
        attr_set = true;
    }

    atom_featurizer_kernel<<<NBLOCKS, NTHREADS, SMEM_BYTES>>>(
        atom_idx, degree_idx, charge_idx, hybrid_idx, numh_idx, chiral_idx,
        bond_counts, scalar3, E_atom, E_deg, E_chg, E_hyb, E_h, E_chi,
        E_bond, Wm, bv, out, n);
}

// round 15
// speedup vs baseline: 1.0241x; 1.0241x over previous
#include <cuda_runtime.h>
#include <cuda_fp16.h>

#define D 128
#define NTHREADS 256
#define CTAS_PER_SM 4
#define NBLOCKS (152 * CTAS_PER_SM)

// Combined fp16 tables (rows of 128 halves = 256B)
#define R_T1 46
#define R_DH 18
#define R_HC 20
#define R_CG 11
#define R_B0 25
#define R_B1 25
#define R_TOT (R_T1 + R_DH + R_HC + R_CG + R_B0 + R_B1)   // 145

#define ROW_T1 0
#define ROW_DH (ROW_T1 + R_T1)   // 46
#define ROW_HC (ROW_DH + R_DH)   // 64
#define ROW_CG (ROW_HC + R_HC)   // 84
#define ROW_B0 (ROW_CG + R_CG)   // 95
#define ROW_B1 (ROW_B0 + R_B0)   // 120

#define SMEM_BYTES (R_TOT * D * 2)         // 37120 -> 4 CTAs/SM

__device__ __forceinline__ unsigned hadd2u(unsigned a, unsigned b) {
    __half2 r = __hadd2(*reinterpret_cast<__half2*>(&a),
                        *reinterpret_cast<__half2*>(&b));
    return *reinterpret_cast<unsigned*>(&r);
}
__device__ __forceinline__ uint4 hadd8(uint4 a, uint4 b) {
    uint4 r;
    r.x = hadd2u(a.x, b.x); r.y = hadd2u(a.y, b.y);
    r.z = hadd2u(a.z, b.z); r.w = hadd2u(a.w, b.w);
    return r;
}
__device__ __forceinline__ float2 h2_as_f2(unsigned u) {
    return __half22float2(*reinterpret_cast<__half2*>(&u));
}
// Packed fp32 add (Blackwell f32x2) — one instruction for two lanes.
// mov.b64 pack/unpack are register-pair aliases (no SASS cost).
__device__ __forceinline__ float2 addx2(float2 a, float2 b) {
    unsigned long long ua, ub, uc;
    asm("mov.b64 %0, {%1, %2};" : "=l"(ua) : "f"(a.x), "f"(a.y));
    asm("mov.b64 %0, {%1, %2};" : "=l"(ub) : "f"(b.x), "f"(b.y));
    asm("add.rn.f32x2 %0, %1, %2;" : "=l"(uc) : "l"(ua), "l"(ub));
    float2 c;
    asm("mov.b64 {%0, %1}, %2;" : "=f"(c.x), "=f"(c.y) : "l"(uc));
    return c;
}

// Per-lane coalesced metadata load for one atom.
// p bits: ai[0:6) rdh[6:11) rhc[11:16) ci[16:20) rb0[20:25) rb1[25:30)
// s01 = half2(s0,s1), s2x2 = half2(s2,s2) — converted once at prefetch.
__device__ __forceinline__ void load_meta_lane(
    long a, long n, unsigned& p, unsigned& s01, unsigned& s2x2,
    const int* __restrict__ atom_idx, const int* __restrict__ degree_idx,
    const int* __restrict__ charge_idx, const int* __restrict__ hybrid_idx,
    const int* __restrict__ numh_idx, const int* __restrict__ chiral_idx,
    const int* __restrict__ bond_counts, const float* __restrict__ scalar3)
{
    if (a < n) {
        const int ai = __ldcs(atom_idx + a);
        const int di = __ldcs(degree_idx + a);
        const int ci = __ldcs(charge_idx + a);
        const int hi = __ldcs(hybrid_idx + a);
        const int ni = __ldcs(numh_idx + a);
        const int xi = __ldcs(chiral_idx + a);
        const int4 bc = __ldcs(reinterpret_cast<const int4*>(bond_counts) + a);
        p = (unsigned)ai
          | ((unsigned)(di * 3 + hi)     << 6)
          | ((unsigned)(ni * 4 + xi)     << 11)
          | ((unsigned)ci                << 16)
          | ((unsigned)(bc.x * 5 + bc.y) << 20)
          | ((unsigned)(bc.z * 5 + bc.w) << 25);
        const float f0 = __ldcs(scalar3 + 3 * a + 0);
        const float f1 = __ldcs(scalar3 + 3 * a + 1);
        const float f2 = __ldcs(scalar3 + 3 * a + 2);
        __half2 h01 = __floats2half2_rn(f0, f1);
        __half2 h22 = __float2half2_rn(f2);
        s01 = *reinterpret_cast<unsigned*>(&h01);
        s2x2 = *reinterpret_cast<unsigned*>(&h22);
    } else {
        p = 0u; s01 = 0u; s2x2 = 0u;
    }
}

__global__ void __launch_bounds__(NTHREADS, CTAS_PER_SM)
atom_featurizer_kernel(
    const int* __restrict__ atom_idx,
    const int* __restrict__ degree_idx,
    const int* __restrict__ charge_idx,
    const int* __restrict__ hybrid_idx,
    const int* __restrict__ numh_idx,
    const int* __restrict__ chiral_idx,
    const int* __restrict__ bond_counts,
    const float* __restrict__ scalar3,
    const float* __restrict__ E_atom,
    const float* __restrict__ E_deg,
    const float* __restrict__ E_chg,
    const float* __restrict__ E_hyb,
    const float* __restrict__ E_h,
    const float* __restrict__ E_chi,
    const float* __restrict__ E_bond,
    const float* __restrict__ Wm,
    const float* __restrict__ bv,
    float* __restrict__ out,
    long n)
{
    extern __shared__ __align__(16) char smem_raw[];
    __half* sh = reinterpret_cast<__half*>(smem_raw);

    const int t = threadIdx.x;

    // ---- Build combined fp16 tables (once per persistent CTA) ----
    for (int e = t; e < R_TOT * D; e += NTHREADS) {
        const int row = e >> 7, col = e & (D - 1);
        float v;
        if (row < ROW_DH) {
            v = E_atom[row * D + col] + bv[col];
        } else if (row < ROW_CG) {
            if (row < ROW_HC) {
                int r = row - ROW_DH;
                v = E_deg[(r / 3) * D + col] + E_hyb[(r % 3) * D + col];
            } else {
                int r = row - ROW_HC;
                v = E_h[(r >> 2) * D + col] + E_chi[(r & 3) * D + col];
            }
        } else if (row < ROW_B0) {
            v = E_chg[(row - ROW_CG) * D + col];
        } else if (row < ROW_B1) {
            int r = row - ROW_B0;
            int c0 = r / 5, c1 = r % 5;
            v = 0.25f * (c0 * Wm[3 * D + col] + c1 * Wm[4 * D + col]);
            if (c0 > 0) v += E_bond[c0 * D + col];
            if (c1 > 0) v += E_bond[c1 * D + col];
        } else {
            int r = row - ROW_B1;
            int c2 = r / 5, c3 = r % 5;
            v = 0.25f * (c2 * Wm[5 * D + col] + c3 * Wm[6 * D + col]);
            if (c2 > 0) v += E_bond[c2 * D + col];
            if (c3 > 0) v += E_bond[c3 * D + col];
        }
        sh[e] = __float2half_rn(v);
    }

    const int lane = t & 31;
    const int warp = t >> 5;
    const int j = lane & 15;       // 16B chunk within row (dims [8j, 8j+8))
    const int sub = lane >> 4;     // 0 -> even atom, 1 -> odd atom

    // W rows 0..2 slices as half2 registers
    __half2 w0h[4], w1h[4], w2h[4];
    #pragma unroll
    for (int q = 0; q < 4; q++) {
        w0h[q] = __floats2half2_rn(Wm[0 * D + j * 8 + 2 * q],
                                   Wm[0 * D + j * 8 + 2 * q + 1]);
        w1h[q] = __floats2half2_rn(Wm[1 * D + j * 8 + 2 * q],
                                   Wm[1 * D + j * 8 + 2 * q + 1]);
        w2h[q] = __floats2half2_rn(Wm[2 * D + j * 8 + 2 * q],
                                   Wm[2 * D + j * 8 + 2 * q + 1]);
    }

    __syncthreads();   // tables ready; no barriers after this point

    const uint4* tab = reinterpret_cast<const uint4*>(sh);  // 16 uint4 per row
    float4* out4 = reinterpret_cast<float4*>(out);

    // Persistent warps, chunks of 32 atoms
    const long nchunks = (n + 31) >> 5;
    const long nwarps = (long)gridDim.x * (NTHREADS / 32);
    long chunk = (long)blockIdx.x * (NTHREADS / 32) + warp;

    // Prefetch chunk 0 metadata (one atom per lane, coalesced)
    unsigned cp, cs01, cs2;
    if (chunk < nchunks)
        load_meta_lane(chunk * 32 + lane, n, cp, cs01, cs2,
                       atom_idx, degree_idx, charge_idx, hybrid_idx,
                       numh_idx, chiral_idx, bond_counts, scalar3);

    for (; chunk < nchunks; chunk += nwarps) {
        // Issue next chunk's loads; they complete under this chunk's compute
        unsigned np, ns01, ns2;
        const long nxt = chunk + nwarps;
        if (nxt < nchunks)
            load_meta_lane(nxt * 32 + lane, n, np, ns01, ns2,
                           atom_idx, degree_idx, charge_idx, hybrid_idx,
                           numh_idx, chiral_idx, bond_counts, scalar3);

        const long gbase = chunk * 32;

        #pragma unroll 4
        for (int k = 0; k < 16; k++) {
            const int src = 2 * k + sub;           // atom-in-chunk for this half-warp
            const long g = gbase + src;

            const unsigned p   = __shfl_sync(0xffffffffu, cp,   src);
            const unsigned s01 = __shfl_sync(0xffffffffu, cs01, src);
            const unsigned s2u = __shfl_sync(0xffffffffu, cs2,  src);

            const int i1 =  p        & 63;
            const int i2 = ((p >> 6)  & 31) + ROW_DH;
            const int i3 = ((p >> 11) & 31) + ROW_HC;
            const int i4 = ((p >> 16) & 15) + ROW_CG;
            const int i5 = ((p >> 20) & 31) + ROW_B0;
            const int i6 = ((p >> 25) & 31) + ROW_B1;

            // 6 independent LDS.128 for max MLP
            const uint4 t1 = tab[i1 * 16 + j];
            const uint4 dh = tab[i2 * 16 + j];
            const uint4 hc = tab[i3 * 16 + j];
            const uint4 cg = tab[i4 * 16 + j];
            const uint4 b0 = tab[i5 * 16 + j];
            const uint4 b1 = tab[i6 * 16 + j];

            // Subtree A: categorical lookups
            const uint4 sA = hadd8(hadd8(t1, dh), hadd8(hc, cg));
            // Subtree B: bond tables + s.W in half2
            uint4 sB = hadd8(b0, b1);
            {
                const __half2 h01 = *reinterpret_cast<const __half2*>(&s01);
                const __half2 s0h = __low2half2(h01);
                const __half2 s1h = __high2half2(h01);
                const __half2 s2h = *reinterpret_cast<const __half2*>(&s2u);
                unsigned* sw = &sB.x;
                #pragma unroll
                for (int q = 0; q < 4; q++) {
                    __half2 acc = __hmul2(s0h, w0h[q]);
                    acc = __hfma2(s1h, w1h[q], acc);
                    acc = __hfma2(s2h, w2h[q], acc);
                    sw[q] = hadd2u(sw[q], *reinterpret_cast<unsigned*>(&acc));
                }
            }

            // fp32 combine via packed f32x2 adds (same precision as scalar FADD)
            const float2 r0 = addx2(h2_as_f2(sA.x), h2_as_f2(sB.x));
            const float2 r1 = addx2(h2_as_f2(sA.y), h2_as_f2(sB.y));
            const float2 r2 = addx2(h2_as_f2(sA.z), h2_as_f2(sB.z));
            const float2 r3 = addx2(h2_as_f2(sA.w), h2_as_f2(sB.w));

            if (g < n) {
                __stcs(&out4[g * 32 + j * 2],     make_float4(r0.x, r0.y, r1.x, r1.y));
                __stcs(&out4[g * 32 + j * 2 + 1], make_float4(r2.x, r2.y, r3.x, r3.y));
            }
        }

        cp = np; cs01 = ns01; cs2 = ns2;
    }
}

extern "C" void kernel_launch(void* const* d_in, const int* in_sizes, int n_in,
                              void* d_out, int out_size) {
    const int*   atom_idx    = (const int*)d_in[0];
    const int*   degree_idx  = (const int*)d_in[1];
    const int*   charge_idx  = (const int*)d_in[2];
    const int*   hybrid_idx  = (const int*)d_in[3];
    const int*   numh_idx    = (const int*)d_in[4];
    const int*   chiral_idx  = (const int*)d_in[5];
    const int*   bond_counts = (const int*)d_in[6];
    const float* scalar3     = (const float*)d_in[7];
    const float* E_atom      = (const float*)d_in[8];
    const float* E_deg       = (const float*)d_in[9];
    const float* E_chg       = (const float*)d_in[10];
    const float* E_hyb       = (const float*)d_in[11];
    const float* E_h         = (const float*)d_in[12];
    const float* E_chi       = (const float*)d_in[13];
    const float* E_bond      = (const float*)d_in[14];
    const float* Wm          = (const float*)d_in[15];
    const float* bv          = (const float*)d_in[16];
    float* out = (float*)d_out;

    const long n = in_sizes[0];

    static bool attr_set = false;
    if (!attr_set) {
        cudaFuncSetAttribute(atom_featurizer_kernel,
                             cudaFuncAttributeMaxDynamicSharedMemorySize, SMEM_BYTES);
        attr_set = true;
    }

    atom_featurizer_kernel<<<NBLOCKS, NTHREADS, SMEM_BYTES>>>(
        atom_idx, degree_idx, charge_idx, hybrid_idx, numh_idx, chiral_idx,
        bond_counts, scalar3, E_atom, E_deg, E_chg, E_hyb, E_h, E_chi,
        E_bond, Wm, bv, out, n);
}

// round 16
// speedup vs baseline: 1.0363x; 1.0119x over previous
#include <cuda_runtime.h>
#include <cuda_fp16.h>

#define D 128
#define NTHREADS 256
#define CTAS_PER_SM 4
#define NBLOCKS (152 * CTAS_PER_SM)

// Combined fp16 tables (rows of 128 halves = 256B)
#define R_T1 46
#define R_DH 18
#define R_HC 20
#define R_CG 11
#define R_B0 25
#define R_B1 25
#define R_TOT (R_T1 + R_DH + R_HC + R_CG + R_B0 + R_B1)   // 145

#define ROW_T1 0
#define ROW_DH (ROW_T1 + R_T1)   // 46
#define ROW_HC (ROW_DH + R_DH)   // 64
#define ROW_CG (ROW_HC + R_HC)   // 84
#define ROW_B0 (ROW_CG + R_CG)   // 95
#define ROW_B1 (ROW_B0 + R_B0)   // 120

#define SMEM_BYTES (R_TOT * D * 2)         // 37120 -> 4 CTAs/SM

__device__ __forceinline__ unsigned hadd2u(unsigned a, unsigned b) {
    __half2 r = __hadd2(*reinterpret_cast<__half2*>(&a),
                        *reinterpret_cast<__half2*>(&b));
    return *reinterpret_cast<unsigned*>(&r);
}
__device__ __forceinline__ uint4 hadd8(uint4 a, uint4 b) {
    uint4 r;
    r.x = hadd2u(a.x, b.x); r.y = hadd2u(a.y, b.y);
    r.z = hadd2u(a.z, b.z); r.w = hadd2u(a.w, b.w);
    return r;
}
__device__ __forceinline__ float lo2f(unsigned u) {
    return __low2float(*reinterpret_cast<__half2*>(&u));
}
__device__ __forceinline__ float hi2f(unsigned u) {
    return __high2float(*reinterpret_cast<__half2*>(&u));
}

// Per-lane coalesced metadata load for one atom.
// pack bits: ai[0:6) rdh[6:11) rhc[11:16) ci[16:20) rb0[20:25) rb1[25:30)
__device__ __forceinline__ void load_meta_lane(
    long a, long n, float& s0, float& s1, float& s2, unsigned& p,
    const int* __restrict__ atom_idx, const int* __restrict__ degree_idx,
    const int* __restrict__ charge_idx, const int* __restrict__ hybrid_idx,
    const int* __restrict__ numh_idx, const int* __restrict__ chiral_idx,
    const int* __restrict__ bond_counts, const float* __restrict__ scalar3)
{
    if (a < n) {
        const int ai = __ldcs(atom_idx + a);
        const int di = __ldcs(degree_idx + a);
        const int ci = __ldcs(charge_idx + a);
        const int hi = __ldcs(hybrid_idx + a);
        const int ni = __ldcs(numh_idx + a);
        const int xi = __ldcs(chiral_idx + a);
        const int4 bc = __ldcs(reinterpret_cast<const int4*>(bond_counts) + a);
        p = (unsigned)ai
          | ((unsigned)(di * 3 + hi)     << 6)
          | ((unsigned)(ni * 4 + xi)     << 11)
          | ((unsigned)ci                << 16)
          | ((unsigned)(bc.x * 5 + bc.y) << 20)
          | ((unsigned)(bc.z * 5 + bc.w) << 25);
        s0 = __ldcs(scalar3 + 3 * a + 0);
        s1 = __ldcs(scalar3 + 3 * a + 1);
        s2 = __ldcs(scalar3 + 3 * a + 2);
    } else {
        p = 0u; s0 = 0.f; s1 = 0.f; s2 = 0.f;
    }
}

__global__ void __launch_bounds__(NTHREADS, CTAS_PER_SM)
atom_featurizer_kernel(
    const int* __restrict__ atom_idx,
    const int* __restrict__ degree_idx,
    const int* __restrict__ charge_idx,
    const int* __restrict__ hybrid_idx,
    const int* __restrict__ numh_idx,
    const int* __restrict__ chiral_idx,
    const int* __restrict__ bond_counts,
    const float* __restrict__ scalar3,
    const float* __restrict__ E_atom,
    const float* __restrict__ E_deg,
    const float* __restrict__ E_chg,
    const float* __restrict__ E_hyb,
    const float* __restrict__ E_h,
    const float* __restrict__ E_chi,
    const float* __restrict__ E_bond,
    const float* __restrict__ Wm,
    const float* __restrict__ bv,
    float* __restrict__ out,
    long n)
{
    extern __shared__ __align__(16) char smem_raw[];
    __half* sh = reinterpret_cast<__half*>(smem_raw);

    const int t = threadIdx.x;

    // ---- Build combined fp16 tables (once per persistent CTA) ----
    for (int e = t; e < R_TOT * D; e += NTHREADS) {
        const int row = e >> 7, col = e & (D - 1);
        float v;
        if (row < ROW_DH) {
            v = E_atom[row * D + col] + bv[col];
        } else if (row < ROW_CG) {
            if (row < ROW_HC) {
                int r = row - ROW_DH;
                v = E_deg[(r / 3) * D + col] + E_hyb[(r % 3) * D + col];
            } else {
                int r = row - ROW_HC;
                v = E_h[(r >> 2) * D + col] + E_chi[(r & 3) * D + col];
            }
        } else if (row < ROW_B0) {
            v = E_chg[(row - ROW_CG) * D + col];
        } else if (row < ROW_B1) {
            int r = row - ROW_B0;
            int c0 = r / 5, c1 = r % 5;
            v = 0.25f * (c0 * Wm[3 * D + col] + c1 * Wm[4 * D + col]);
            if (c0 > 0) v += E_bond[c0 * D + col];
            if (c1 > 0) v += E_bond[c1 * D + col];
        } else {
            int r = row - ROW_B1;
            int c2 = r / 5, c3 = r % 5;
            v = 0.25f * (c2 * Wm[5 * D + col] + c3 * Wm[6 * D + col]);
            if (c2 > 0) v += E_bond[c2 * D + col];
            if (c3 > 0) v += E_bond[c3 * D + col];
        }
        sh[e] = __float2half_rn(v);
    }

    const int lane = t & 31;
    const int warp = t >> 5;
    const int j = lane & 15;       // 16B chunk within row (dims [8j, 8j+8))
    const int sub = lane >> 4;     // 0 -> even atom, 1 -> odd atom

    // W rows 0..2 slices as half2 registers
    __half2 w0h[4], w1h[4], w2h[4];
    #pragma unroll
    for (int q = 0; q < 4; q++) {
        w0h[q] = __floats2half2_rn(Wm[0 * D + j * 8 + 2 * q],
                                   Wm[0 * D + j * 8 + 2 * q + 1]);
        w1h[q] = __floats2half2_rn(Wm[1 * D + j * 8 + 2 * q],
                                   Wm[1 * D + j * 8 + 2 * q + 1]);
        w2h[q] = __floats2half2_rn(Wm[2 * D + j * 8 + 2 * q],
                                   Wm[2 * D + j * 8 + 2 * q + 1]);
    }

    __syncthreads();   // tables ready; no barriers after this point

    const uint4* tab = reinterpret_cast<const uint4*>(sh);  // 16 uint4 per row
    float4* out4 = reinterpret_cast<float4*>(out);

    // Persistent warps, chunks of 32 atoms
    const long nchunks = (n + 31) >> 5;
    const long nwarps = (long)gridDim.x * (NTHREADS / 32);
    long chunk = (long)blockIdx.x * (NTHREADS / 32) + warp;

    // Prefetch chunk 0 metadata (one atom per lane, coalesced)
    float cs0, cs1, cs2; unsigned cp;
    if (chunk < nchunks)
        load_meta_lane(chunk * 32 + lane, n, cs0, cs1, cs2, cp,
                       atom_idx, degree_idx, charge_idx, hybrid_idx,
                       numh_idx, chiral_idx, bond_counts, scalar3);

    for (; chunk < nchunks; chunk += nwarps) {
        // Issue next chunk's loads; they complete under this chunk's compute
        float ns0, ns1, ns2; unsigned np;
        const long nxt = chunk + nwarps;
        if (nxt < nchunks)
            load_meta_lane(nxt * 32 + lane, n, ns0, ns1, ns2, np,
                           atom_idx, degree_idx, charge_idx, hybrid_idx,
                           numh_idx, chiral_idx, bond_counts, scalar3);

        const long gbase = chunk * 32;

        #pragma unroll 4
        for (int k = 0; k < 16; k++) {
            const int src = 2 * k + sub;           // atom-in-chunk for this half-warp
            const long g = gbase + src;

            const float    m0 = __shfl_sync(0xffffffffu, cs0, src);
            const float    m1 = __shfl_sync(0xffffffffu, cs1, src);
            const float    m2 = __shfl_sync(0xffffffffu, cs2, src);
            const unsigned p  = __shfl_sync(0xffffffffu, cp,  src);

            const int i1 =  p        & 63;
            const int i2 = ((p >> 6)  & 31) + ROW_DH;
            const int i3 = ((p >> 11) & 31) + ROW_HC;
            const int i4 = ((p >> 16) & 15) + ROW_CG;
            const int i5 = ((p >> 20) & 31) + ROW_B0;
            const int i6 = ((p >> 25) & 31) + ROW_B1;

            const uint4 t1 = tab[i1 * 16 + j];
            const uint4 dh = tab[i2 * 16 + j];
            const uint4 hc = tab[i3 * 16 + j];
            const uint4 cg = tab[i4 * 16 + j];
            const uint4 b0 = tab[i5 * 16 + j];
            const uint4 b1 = tab[i6 * 16 + j];

            // Subtree A: categorical lookups
            const uint4 sA = hadd8(hadd8(t1, dh), hadd8(hc, cg));
            // Subtree B: bond tables + s.W in half2
            uint4 sB = hadd8(b0, b1);
            {
                const __half2 s0h = __float2half2_rn(m0);
                const __half2 s1h = __float2half2_rn(m1);
                const __half2 s2h = __float2half2_rn(m2);
                unsigned* sw = &sB.x;
                #pragma unroll
                for (int q = 0; q < 4; q++) {
                    __half2 acc = __hmul2(s0h, w0h[q]);
                    acc = __hfma2(s1h, w1h[q], acc);
                    acc = __hfma2(s2h, w2h[q], acc);
                    sw[q] = hadd2u(sw[q], *reinterpret_cast<unsigned*>(&acc));
                }
            }

            // fp32 combine
            float4 olo, ohi;
            olo.x = lo2f(sA.x) + lo2f(sB.x);
            olo.y = hi2f(sA.x) + hi2f(sB.x);
            olo.z = lo2f(sA.y) + lo2f(sB.y);
            olo.w = hi2f(sA.y) + hi2f(sB.y);
            ohi.x = lo2f(sA.z) + lo2f(sB.z);
            ohi.y = hi2f(sA.z) + hi2f(sB.z);
            ohi.z = lo2f(sA.w) + lo2f(sB.w);
            ohi.w = hi2f(sA.w) + hi2f(sB.w);

            if (g < n) {
                __stcs(&out4[g * 32 + j * 2],     olo);
                __stcs(&out4[g * 32 + j * 2 + 1], ohi);
            }
        }

        cs0 = ns0; cs1 = ns1; cs2 = ns2; cp = np;
    }
}

extern "C" void kernel_launch(void* const* d_in, const int* in_sizes, int n_in,
                              void* d_out, int out_size) {
    const int*   atom_idx    = (const int*)d_in[0];
    const int*   degree_idx  = (const int*)d_in[1];
    const int*   charge_idx  = (const int*)d_in[2];
    const int*   hybrid_idx  = (const int*)d_in[3];
    const int*   numh_idx    = (const int*)d_in[4];
    const int*   chiral_idx  = (const int*)d_in[5];
    const int*   bond_counts = (const int*)d_in[6];
    const float* scalar3     = (const float*)d_in[7];
    const float* E_atom      = (const float*)d_in[8];
    const float* E_deg       = (const float*)d_in[9];
    const float* E_chg       = (const float*)d_in[10];
    const float* E_hyb       = (const float*)d_in[11];
    const float* E_h         = (const float*)d_in[12];
    const float* E_chi       = (const float*)d_in[13];
    const float* E_bond      = (const float*)d_in[14];
    const float* Wm          = (const float*)d_in[15];
    const float* bv          = (const float*)d_in[16];
    float* out = (float*)d_out;

    const long n = in_sizes[0];

    static bool attr_set = false;
    if (!attr_set) {
        cudaFuncSetAttribute(atom_featurizer_kernel,
                             cudaFuncAttributeMaxDynamicSharedMemorySize, SMEM_BYTES);
        attr_set = true;
    }

    atom_featurizer_kernel<<<NBLOCKS, NTHREADS, SMEM_BYTES>>>(
        atom_idx, degree_idx, charge_idx, hybrid_idx, numh_idx, chiral_idx,
        bond_counts, scalar3, E_atom, E_deg, E_chg, E_hyb, E_h, E_chi,
        E_bond, Wm, bv, out, n);
}